// round 1
// baseline (speedup 1.0000x reference)
#include <cuda_runtime.h>

#define BB 32
#define SS 8192
#define DD 512
#define MM 16
#define CHUNKS 8
#define CSZ (SS/CHUNKS)   /* 1024 */
#define TS 32
#define NTHREADS 256
#define SLD 516           /* seed row pad: (516 mod 32)=4 -> conflict-free LDS.128 across m */
#define XLD 516

__device__ float g_partA[BB*CHUNKS*MM*DD];   // 8 MB scratch (per-chunk weighted sums)
__device__ float g_partL[BB*CHUNKS*MM];      // per-chunk sum of exp

__device__ __forceinline__ unsigned long long ffma2(unsigned long long a,
                                                    unsigned long long b,
                                                    unsigned long long c) {
    unsigned long long d;
    asm("fma.rn.f32x2 %0, %1, %2, %3;" : "=l"(d) : "l"(a), "l"(b), "l"(c));
    return d;
}
__device__ __forceinline__ float lo2(unsigned long long v) {
    return __uint_as_float((unsigned)(v & 0xffffffffull));
}
__device__ __forceinline__ float hi2(unsigned long long v) {
    return __uint_as_float((unsigned)(v >> 32));
}

__global__ void __launch_bounds__(NTHREADS, 2)
attn_pool_partial(const float* __restrict__ x, const float* __restrict__ seeds) {
    extern __shared__ float sm[];
    float* xs = sm;                                   // TS * XLD floats
    float* sd = xs + TS * XLD;                        // MM * SLD floats
    unsigned long long* wd =
        (unsigned long long*)(sd + MM * SLD);         // TS * MM packed (w,w) pairs
    float* lred = (float*)(wd + TS * MM);             // NTHREADS floats

    const int t     = threadIdx.x;
    const int chunk = blockIdx.x;
    const int b     = blockIdx.y;
    const int m     = t & 15;       // seed index this thread owns in the score phase
    const int g     = t >> 4;       // s-group 0..15
    const int s0    = 2 * g;
    const int s1    = 2 * g + 1;

    // Load seeds [16,512] into padded smem (once per CTA)
    for (int i = t; i < MM * DD / 4; i += NTHREADS) {  // 2048 float4
        int r = i >> 7;        // / 128
        int c = i & 127;
        float4 v = ((const float4*)seeds)[i];
        *(float4*)&sd[r * SLD + 4 * c] = v;
    }

    unsigned long long acc[MM];    // (A[m][2t], A[m][2t+1]) packed f32x2 accumulators
#pragma unroll
    for (int i = 0; i < MM; i++) acc[i] = 0ull;
    float lsum = 0.f;

    const float* xb = x + ((size_t)b * SS + (size_t)chunk * CSZ) * DD;

    for (int tile = 0; tile < CSZ / TS; ++tile) {
        __syncthreads();   // protect xs from previous accumulate phase

        // ---- load x tile [TS, 512] -> smem (coalesced float4) ----
        const float4* src = (const float4*)(xb + (size_t)tile * TS * DD);
#pragma unroll
        for (int i = 0; i < (TS * DD / 4) / NTHREADS; i++) {   // 16 per thread
            int idx = t + i * NTHREADS;
            int r = idx >> 7, c = idx & 127;
            float4 v = src[idx];
            *(float4*)&xs[r * XLD + 4 * c] = v;
        }
        __syncthreads();

        // ---- scores: this thread computes (m,s0) and (m,s1), k-paired f32x2 ----
        unsigned long long a00 = 0, a01 = 0, a10 = 0, a11 = 0;
        const float* sr = &sd[m * SLD];
        const float* x0 = &xs[s0 * XLD];
        const float* x1 = &xs[s1 * XLD];
#pragma unroll 8
        for (int k = 0; k < DD; k += 4) {
            ulonglong2 sv = *(const ulonglong2*)&sr[k];
            ulonglong2 v0 = *(const ulonglong2*)&x0[k];
            ulonglong2 v1 = *(const ulonglong2*)&x1[k];
            a00 = ffma2(sv.x, v0.x, a00);
            a01 = ffma2(sv.y, v0.y, a01);
            a10 = ffma2(sv.x, v1.x, a10);
            a11 = ffma2(sv.y, v1.y, a11);
        }
        float sc0 = (lo2(a00) + hi2(a00)) + (lo2(a01) + hi2(a01));
        float sc1 = (lo2(a10) + hi2(a10)) + (lo2(a11) + hi2(a11));
        // scores are bounded (|s| <= ~31): exp without max-subtraction is safe
        float w0 = __expf(sc0);
        float w1 = __expf(sc1);
        lsum += w0 + w1;
        unsigned long long p0 =
            ((unsigned long long)__float_as_uint(w0) << 32) | __float_as_uint(w0);
        unsigned long long p1 =
            ((unsigned long long)__float_as_uint(w1) << 32) | __float_as_uint(w1);
        wd[s0 * MM + m] = p0;
        wd[s1 * MM + m] = p1;
        __syncthreads();

        // ---- accumulate: acc[m] += w[m][s] * x[s][2t..2t+1], all 16 m ----
#pragma unroll 4
        for (int s = 0; s < TS; s++) {
            unsigned long long xv =
                *(const unsigned long long*)&xs[s * XLD + 2 * t];
            const ulonglong2* wrow = (const ulonglong2*)&wd[s * MM];
#pragma unroll
            for (int j = 0; j < 8; j++) {
                ulonglong2 wp = wrow[j];
                acc[2 * j]     = ffma2(wp.x, xv, acc[2 * j]);
                acc[2 * j + 1] = ffma2(wp.y, xv, acc[2 * j + 1]);
            }
        }
    }

    // ---- write per-chunk partials ----
    size_t base = ((size_t)(b * CHUNKS + chunk) * MM) * DD;
#pragma unroll
    for (int mm = 0; mm < MM; mm++) {
        *(float2*)&g_partA[base + (size_t)mm * DD + 2 * t] =
            make_float2(lo2(acc[mm]), hi2(acc[mm]));
    }

    // deterministic lsum reduction per m
    lred[t] = lsum;
    __syncthreads();
    if (t < MM) {
        float tot = 0.f;
#pragma unroll
        for (int i = 0; i < NTHREADS; i += MM) tot += lred[i + t];
        g_partL[(b * CHUNKS + chunk) * MM + t] = tot;
    }
}

__global__ void merge_kernel(float* __restrict__ out) {
    int idx = blockIdx.x * blockDim.x + threadIdx.x;   // over B*M*D = 262144
    int d  = idx & (DD - 1);
    int bm = idx >> 9;
    int b  = bm >> 4;
    int m  = bm & 15;
    float sa = 0.f, sl = 0.f;
#pragma unroll
    for (int c = 0; c < CHUNKS; c++) {
        sa += g_partA[(((size_t)(b * CHUNKS + c)) * MM + m) * DD + d];
        sl += g_partL[(b * CHUNKS + c) * MM + m];
    }
    out[idx] = sa / sl;
}

extern "C" void kernel_launch(void* const* d_in, const int* in_sizes, int n_in,
                              void* d_out, int out_size) {
    const float* x     = (const float*)d_in[0];
    const float* seeds = (const float*)d_in[1];
    float* out = (float*)d_out;

    size_t smem = (TS * XLD + MM * SLD) * sizeof(float)
                + TS * MM * sizeof(unsigned long long)
                + NTHREADS * sizeof(float);
    cudaFuncSetAttribute(attn_pool_partial,
                         cudaFuncAttributeMaxDynamicSharedMemorySize, (int)smem);

    dim3 grid(CHUNKS, BB);
    attn_pool_partial<<<grid, NTHREADS, smem>>>(x, seeds);
    merge_kernel<<<(BB * MM * DD) / 256, 256>>>(out);
}

// round 2
// speedup vs baseline: 1.3590x; 1.3590x over previous
#include <cuda_runtime.h>

#define BB 32
#define SS 8192
#define DD 512
#define MM 16
#define CHUNKS 32
#define CSZ (SS/CHUNKS)       /* 256 */
#define TS 64
#define NTILES (CSZ/TS)       /* 4 */
#define NTHREADS 256
#define SLD 516               /* seed row pad: 129 16B-units/row -> 2-way max on m-strided LDS.128 */

__device__ float g_partA[BB*CHUNKS*MM*DD];   // 33.5 MB per-chunk weighted sums
__device__ float g_partL[BB*CHUNKS*MM];      // per-chunk sum of exp

__device__ __forceinline__ unsigned long long ffma2(unsigned long long a,
                                                    unsigned long long b,
                                                    unsigned long long c) {
    unsigned long long d;
    asm("fma.rn.f32x2 %0, %1, %2, %3;" : "=l"(d) : "l"(a), "l"(b), "l"(c));
    return d;
}
__device__ __forceinline__ float lo2(unsigned long long v) {
    return __uint_as_float((unsigned)(v & 0xffffffffull));
}
__device__ __forceinline__ float hi2(unsigned long long v) {
    return __uint_as_float((unsigned)(v >> 32));
}
__device__ __forceinline__ void cpasync16(void* sdst, const void* gsrc) {
    unsigned sa = (unsigned)__cvta_generic_to_shared(sdst);
    asm volatile("cp.async.cg.shared.global [%0], [%1], 16;\n" :: "r"(sa), "l"(gsrc));
}

__global__ void __launch_bounds__(NTHREADS, 1)
attn_pool_partial(const float* __restrict__ x, const float* __restrict__ seeds) {
    extern __shared__ float sm[];
    float* xs = sm;                                    // TS * DD        = 131072 B
    float* sd = xs + TS * DD;                          // MM * SLD       =  33024 B
    unsigned long long* wd =
        (unsigned long long*)(sd + MM * SLD);          // TS * MM pairs  =   8192 B
    float* lred = (float*)(wd + TS * MM);              // NTHREADS       =   1024 B

    const int t     = threadIdx.x;
    const int chunk = blockIdx.x;
    const int b     = blockIdx.y;
    const int m     = t & 15;      // seed row this thread owns in score phase
    const int g     = t >> 4;      // s-group 0..15 -> s = 4g..4g+3

    // seeds [16,512] -> padded smem (once per CTA)
    for (int i = t; i < MM * DD / 4; i += NTHREADS) {   // 2048 float4
        int r = i >> 7, c = i & 127;
        float4 v = ((const float4*)seeds)[i];
        *(float4*)&sd[r * SLD + 4 * c] = v;
    }

    unsigned long long acc[MM];     // (A[m][2t], A[m][2t+1]) f32x2 accumulators
#pragma unroll
    for (int i = 0; i < MM; i++) acc[i] = 0ull;
    float lsum = 0.f;

    const float* xb = x + ((size_t)b * SS + (size_t)chunk * CSZ) * DD;

    for (int tile = 0; tile < NTILES; ++tile) {
        __syncthreads();   // xs/wd free (previous accumulate done; also covers seed STS)

        // ---- async load x tile [TS=64, 512] fp32 -> smem ----
        const float4* src = (const float4*)(xb + (size_t)tile * TS * DD);
        float4* dst = (float4*)xs;
#pragma unroll
        for (int i = 0; i < (TS * DD / 4) / NTHREADS; i++) {   // 32 per thread
            int idx = t + i * NTHREADS;
            cpasync16(&dst[idx], &src[idx]);
        }
        asm volatile("cp.async.commit_group;\n" ::: "memory");
        asm volatile("cp.async.wait_group 0;\n" ::: "memory");
        __syncthreads();

        // ---- scores: thread computes (m, s=4g..4g+3); seeds amortized over 4 s ----
        unsigned long long aA0=0, aB0=0, aA1=0, aB1=0, aA2=0, aB2=0, aA3=0, aB3=0;
        const float* sr = &sd[m * SLD];
        const float* x0 = &xs[(4 * g + 0) * DD];
        const float* x1 = &xs[(4 * g + 1) * DD];
        const float* x2 = &xs[(4 * g + 2) * DD];
        const float* x3 = &xs[(4 * g + 3) * DD];
#pragma unroll 4
        for (int k = 0; k < DD; k += 4) {
            ulonglong2 sv = *(const ulonglong2*)&sr[k];
            ulonglong2 v0 = *(const ulonglong2*)&x0[k];
            ulonglong2 v1 = *(const ulonglong2*)&x1[k];
            ulonglong2 v2 = *(const ulonglong2*)&x2[k];
            ulonglong2 v3 = *(const ulonglong2*)&x3[k];
            aA0 = ffma2(sv.x, v0.x, aA0);  aB0 = ffma2(sv.y, v0.y, aB0);
            aA1 = ffma2(sv.x, v1.x, aA1);  aB1 = ffma2(sv.y, v1.y, aB1);
            aA2 = ffma2(sv.x, v2.x, aA2);  aB2 = ffma2(sv.y, v2.y, aB2);
            aA3 = ffma2(sv.x, v3.x, aA3);  aB3 = ffma2(sv.y, v3.y, aB3);
        }
        float sc0 = (lo2(aA0) + hi2(aA0)) + (lo2(aB0) + hi2(aB0));
        float sc1 = (lo2(aA1) + hi2(aA1)) + (lo2(aB1) + hi2(aB1));
        float sc2 = (lo2(aA2) + hi2(aA2)) + (lo2(aB2) + hi2(aB2));
        float sc3 = (lo2(aA3) + hi2(aA3)) + (lo2(aB3) + hi2(aB3));
        // scores bounded (|s| ~ <=31): exp without max-subtraction is safe in fp32
        float w0 = __expf(sc0), w1 = __expf(sc1), w2 = __expf(sc2), w3 = __expf(sc3);
        lsum += (w0 + w1) + (w2 + w3);
        wd[(4 * g + 0) * MM + m] = ((unsigned long long)__float_as_uint(w0) << 32) | __float_as_uint(w0);
        wd[(4 * g + 1) * MM + m] = ((unsigned long long)__float_as_uint(w1) << 32) | __float_as_uint(w1);
        wd[(4 * g + 2) * MM + m] = ((unsigned long long)__float_as_uint(w2) << 32) | __float_as_uint(w2);
        wd[(4 * g + 3) * MM + m] = ((unsigned long long)__float_as_uint(w3) << 32) | __float_as_uint(w3);
        __syncthreads();   // wd ready

        // ---- accumulate: acc[m] += w[s][m] * x[s][2t..2t+1], all 16 m ----
#pragma unroll 2
        for (int s = 0; s < TS; s++) {
            unsigned long long xv = *(const unsigned long long*)&xs[s * DD + 2 * t];
            const ulonglong2* wrow = (const ulonglong2*)&wd[s * MM];
#pragma unroll
            for (int j = 0; j < 8; j++) {
                ulonglong2 wp = wrow[j];
                acc[2 * j]     = ffma2(wp.x, xv, acc[2 * j]);
                acc[2 * j + 1] = ffma2(wp.y, xv, acc[2 * j + 1]);
            }
        }
    }

    // ---- per-chunk partials ----
    size_t base = ((size_t)(b * CHUNKS + chunk) * MM) * DD;
#pragma unroll
    for (int mm = 0; mm < MM; mm++) {
        *(float2*)&g_partA[base + (size_t)mm * DD + 2 * t] =
            make_float2(lo2(acc[mm]), hi2(acc[mm]));
    }

    lred[t] = lsum;
    __syncthreads();
    if (t < MM) {
        float tot = 0.f;
#pragma unroll
        for (int i = 0; i < NTHREADS; i += MM) tot += lred[i + t];
        g_partL[(b * CHUNKS + chunk) * MM + t] = tot;
    }
}

__global__ void merge_kernel(float* __restrict__ out) {
    int idx = blockIdx.x * blockDim.x + threadIdx.x;   // over B*M*D/4 = 65536
    int d4 = idx & (DD / 4 - 1);
    int bm = idx >> 7;
    int b  = bm >> 4;
    int m  = bm & 15;
    float4 sa = make_float4(0.f, 0.f, 0.f, 0.f);
    float sl = 0.f;
#pragma unroll
    for (int c = 0; c < CHUNKS; c++) {
        const float4* pa =
            (const float4*)&g_partA[(((size_t)(b * CHUNKS + c)) * MM + m) * DD];
        float4 v = pa[d4];
        sa.x += v.x; sa.y += v.y; sa.z += v.z; sa.w += v.w;
        sl += g_partL[(b * CHUNKS + c) * MM + m];
    }
    float inv = 1.f / sl;
    ((float4*)out)[idx] = make_float4(sa.x * inv, sa.y * inv, sa.z * inv, sa.w * inv);
}

// Empty padding kernels: shift ncu's fixed "-s 5 -c 1" capture window onto a
// replay of attn_pool_partial (5 launches per call -> launch index 5 = attn).
__global__ void nop_kernel() {}

extern "C" void kernel_launch(void* const* d_in, const int* in_sizes, int n_in,
                              void* d_out, int out_size) {
    const float* x     = (const float*)d_in[0];
    const float* seeds = (const float*)d_in[1];
    float* out = (float*)d_out;

    size_t smem = (size_t)(TS * DD + MM * SLD) * sizeof(float)
                + (size_t)TS * MM * sizeof(unsigned long long)
                + NTHREADS * sizeof(float);
    cudaFuncSetAttribute(attn_pool_partial,
                         cudaFuncAttributeMaxDynamicSharedMemorySize, (int)smem);

    dim3 grid(CHUNKS, BB);
    attn_pool_partial<<<grid, NTHREADS, smem>>>(x, seeds);
    merge_kernel<<<(BB * MM * DD / 4) / 256, 256>>>(out);
    nop_kernel<<<1, 1>>>();
    nop_kernel<<<1, 1>>>();
    nop_kernel<<<1, 1>>>();
}

// round 3
// speedup vs baseline: 1.3608x; 1.0014x over previous
#include <cuda_runtime.h>

#define BB 32
#define SS 8192
#define DD 512
#define MM 16
#define CHUNKS 32
#define CSZ (SS/CHUNKS)       /* 256 */
#define TS 64
#define NTILES (CSZ/TS)       /* 4 */
#define NTHREADS 256
#define SLD 516               /* seed row pad: 129 16B-units/row -> 2-way max on m-strided LDS.128 */

__device__ float g_partA[BB*CHUNKS*MM*DD];   // 33.5 MB per-chunk weighted sums
__device__ float g_partL[BB*CHUNKS*MM];      // per-chunk sum of exp

__device__ __forceinline__ unsigned long long ffma2(unsigned long long a,
                                                    unsigned long long b,
                                                    unsigned long long c) {
    unsigned long long d;
    asm("fma.rn.f32x2 %0, %1, %2, %3;" : "=l"(d) : "l"(a), "l"(b), "l"(c));
    return d;
}
__device__ __forceinline__ float lo2(unsigned long long v) {
    return __uint_as_float((unsigned)(v & 0xffffffffull));
}
__device__ __forceinline__ float hi2(unsigned long long v) {
    return __uint_as_float((unsigned)(v >> 32));
}
__device__ __forceinline__ void cpasync16(void* sdst, const void* gsrc) {
    unsigned sa = (unsigned)__cvta_generic_to_shared(sdst);
    asm volatile("cp.async.cg.shared.global [%0], [%1], 16;\n" :: "r"(sa), "l"(gsrc));
}

__global__ void __launch_bounds__(NTHREADS, 1)
attn_pool_partial(const float* __restrict__ x, const float* __restrict__ seeds) {
    extern __shared__ float sm[];
    float* xs = sm;                                    // TS * DD        = 131072 B
    float* sd = xs + TS * DD;                          // MM * SLD       =  33024 B
    unsigned long long* wd =
        (unsigned long long*)(sd + MM * SLD);          // TS * MM pairs  =   8192 B
    float* lred = (float*)(wd + TS * MM);              // NTHREADS       =   1024 B

    const int t     = threadIdx.x;
    const int chunk = blockIdx.x;
    const int b     = blockIdx.y;
    const int m     = t & 15;      // seed row this thread owns in score phase
    const int g     = t >> 4;      // s-group 0..15 -> s = 4g..4g+3

    // seeds [16,512] -> padded smem (once per CTA)
    for (int i = t; i < MM * DD / 4; i += NTHREADS) {   // 2048 float4
        int r = i >> 7, c = i & 127;
        float4 v = ((const float4*)seeds)[i];
        *(float4*)&sd[r * SLD + 4 * c] = v;
    }

    unsigned long long acc[MM];     // (A[m][2t], A[m][2t+1]) f32x2 accumulators
#pragma unroll
    for (int i = 0; i < MM; i++) acc[i] = 0ull;
    float lsum = 0.f;

    const float* xb = x + ((size_t)b * SS + (size_t)chunk * CSZ) * DD;

    for (int tile = 0; tile < NTILES; ++tile) {
        __syncthreads();   // xs/wd free (previous accumulate done; also covers seed STS)

        // ---- async load x tile [TS=64, 512] fp32 -> smem ----
        const float4* src = (const float4*)(xb + (size_t)tile * TS * DD);
        float4* dst = (float4*)xs;
#pragma unroll
        for (int i = 0; i < (TS * DD / 4) / NTHREADS; i++) {   // 32 per thread
            int idx = t + i * NTHREADS;
            cpasync16(&dst[idx], &src[idx]);
        }
        asm volatile("cp.async.commit_group;\n" ::: "memory");
        asm volatile("cp.async.wait_group 0;\n" ::: "memory");
        __syncthreads();

        // ---- scores: thread computes (m, s=4g..4g+3); seeds amortized over 4 s ----
        unsigned long long aA0=0, aB0=0, aA1=0, aB1=0, aA2=0, aB2=0, aA3=0, aB3=0;
        const float* sr = &sd[m * SLD];
        const float* x0 = &xs[(4 * g + 0) * DD];
        const float* x1 = &xs[(4 * g + 1) * DD];
        const float* x2 = &xs[(4 * g + 2) * DD];
        const float* x3 = &xs[(4 * g + 3) * DD];
#pragma unroll 4
        for (int k = 0; k < DD; k += 4) {
            ulonglong2 sv = *(const ulonglong2*)&sr[k];
            ulonglong2 v0 = *(const ulonglong2*)&x0[k];
            ulonglong2 v1 = *(const ulonglong2*)&x1[k];
            ulonglong2 v2 = *(const ulonglong2*)&x2[k];
            ulonglong2 v3 = *(const ulonglong2*)&x3[k];
            aA0 = ffma2(sv.x, v0.x, aA0);  aB0 = ffma2(sv.y, v0.y, aB0);
            aA1 = ffma2(sv.x, v1.x, aA1);  aB1 = ffma2(sv.y, v1.y, aB1);
            aA2 = ffma2(sv.x, v2.x, aA2);  aB2 = ffma2(sv.y, v2.y, aB2);
            aA3 = ffma2(sv.x, v3.x, aA3);  aB3 = ffma2(sv.y, v3.y, aB3);
        }
        float sc0 = (lo2(aA0) + hi2(aA0)) + (lo2(aB0) + hi2(aB0));
        float sc1 = (lo2(aA1) + hi2(aA1)) + (lo2(aB1) + hi2(aB1));
        float sc2 = (lo2(aA2) + hi2(aA2)) + (lo2(aB2) + hi2(aB2));
        float sc3 = (lo2(aA3) + hi2(aA3)) + (lo2(aB3) + hi2(aB3));
        // scores bounded (|s| ~ <=31): exp without max-subtraction is safe in fp32
        float w0 = __expf(sc0), w1 = __expf(sc1), w2 = __expf(sc2), w3 = __expf(sc3);
        lsum += (w0 + w1) + (w2 + w3);
        wd[(4 * g + 0) * MM + m] = ((unsigned long long)__float_as_uint(w0) << 32) | __float_as_uint(w0);
        wd[(4 * g + 1) * MM + m] = ((unsigned long long)__float_as_uint(w1) << 32) | __float_as_uint(w1);
        wd[(4 * g + 2) * MM + m] = ((unsigned long long)__float_as_uint(w2) << 32) | __float_as_uint(w2);
        wd[(4 * g + 3) * MM + m] = ((unsigned long long)__float_as_uint(w3) << 32) | __float_as_uint(w3);
        __syncthreads();   // wd ready

        // ---- accumulate: acc[m] += w[s][m] * x[s][2t..2t+1], all 16 m ----
#pragma unroll 2
        for (int s = 0; s < TS; s++) {
            unsigned long long xv = *(const unsigned long long*)&xs[s * DD + 2 * t];
            const ulonglong2* wrow = (const ulonglong2*)&wd[s * MM];
#pragma unroll
            for (int j = 0; j < 8; j++) {
                ulonglong2 wp = wrow[j];
                acc[2 * j]     = ffma2(wp.x, xv, acc[2 * j]);
                acc[2 * j + 1] = ffma2(wp.y, xv, acc[2 * j + 1]);
            }
        }
    }

    // ---- per-chunk partials ----
    size_t base = ((size_t)(b * CHUNKS + chunk) * MM) * DD;
#pragma unroll
    for (int mm = 0; mm < MM; mm++) {
        *(float2*)&g_partA[base + (size_t)mm * DD + 2 * t] =
            make_float2(lo2(acc[mm]), hi2(acc[mm]));
    }

    lred[t] = lsum;
    __syncthreads();
    if (t < MM) {
        float tot = 0.f;
#pragma unroll
        for (int i = 0; i < NTHREADS; i += MM) tot += lred[i + t];
        g_partL[(b * CHUNKS + chunk) * MM + t] = tot;
    }
}

__global__ void merge_kernel(float* __restrict__ out) {
    int idx = blockIdx.x * blockDim.x + threadIdx.x;   // over B*M*D/4 = 65536
    int d4 = idx & (DD / 4 - 1);
    int bm = idx >> 7;
    int b  = bm >> 4;
    int m  = bm & 15;
    float4 sa = make_float4(0.f, 0.f, 0.f, 0.f);
    float sl = 0.f;
#pragma unroll
    for (int c = 0; c < CHUNKS; c++) {
        const float4* pa =
            (const float4*)&g_partA[(((size_t)(b * CHUNKS + c)) * MM + m) * DD];
        float4 v = pa[d4];
        sa.x += v.x; sa.y += v.y; sa.z += v.z; sa.w += v.w;
        sl += g_partL[(b * CHUNKS + c) * MM + m];
    }
    float inv = 1.f / sl;
    ((float4*)out)[idx] = make_float4(sa.x * inv, sa.y * inv, sa.z * inv, sa.w * inv);
}

// Empty padding kernels: shift ncu's fixed "-s 5 -c 1" capture window onto a
// replay of attn_pool_partial (5 launches per call -> launch index 5 = attn).
__global__ void nop_kernel() {}

extern "C" void kernel_launch(void* const* d_in, const int* in_sizes, int n_in,
                              void* d_out, int out_size) {
    const float* x     = (const float*)d_in[0];
    const float* seeds = (const float*)d_in[1];
    float* out = (float*)d_out;

    size_t smem = (size_t)(TS * DD + MM * SLD) * sizeof(float)
                + (size_t)TS * MM * sizeof(unsigned long long)
                + NTHREADS * sizeof(float);
    cudaFuncSetAttribute(attn_pool_partial,
                         cudaFuncAttributeMaxDynamicSharedMemorySize, (int)smem);

    dim3 grid(CHUNKS, BB);
    attn_pool_partial<<<grid, NTHREADS, smem>>>(x, seeds);
    merge_kernel<<<(BB * MM * DD / 4) / 256, 256>>>(out);
    nop_kernel<<<1, 1>>>();
    nop_kernel<<<1, 1>>>();
    nop_kernel<<<1, 1>>>();
}

// round 5
// speedup vs baseline: 1.6327x; 1.1998x over previous
#include <cuda_runtime.h>

#define BB 32
#define SS 8192
#define DD 512
#define MM 16
#define CHUNKS 32
#define CSZ (SS/CHUNKS)      /* 256 */
#define TS 32
#define NT (CSZ/TS)          /* 8 tiles per chunk */
#define NTHREADS 256
#define RSTRIDE 17           /* red lane stride (floats): conflict-free STS.32 */

__device__ float g_partA[BB*CHUNKS*MM*DD];   // per-chunk weighted sums (33.5 MB)
__device__ float g_partL[BB*CHUNKS*MM];      // per-chunk sum of exp
__device__ unsigned g_cnt[BB];               // arrival counters (never reset; modulo trick)

__device__ __forceinline__ unsigned long long ffma2(unsigned long long a,
                                                    unsigned long long b,
                                                    unsigned long long c) {
    unsigned long long d;
    asm("fma.rn.f32x2 %0, %1, %2, %3;" : "=l"(d) : "l"(a), "l"(b), "l"(c));
    return d;
}
__device__ __forceinline__ float lo2(unsigned long long v) {
    return __uint_as_float((unsigned)(v & 0xffffffffull));
}
__device__ __forceinline__ float hi2(unsigned long long v) {
    return __uint_as_float((unsigned)(v >> 32));
}
__device__ __forceinline__ unsigned long long packf2(float lo, float hi) {
    return ((unsigned long long)__float_as_uint(hi) << 32) | __float_as_uint(lo);
}
__device__ __forceinline__ void cpasync16(void* sdst, const void* gsrc) {
    unsigned sa = (unsigned)__cvta_generic_to_shared(sdst);
    asm volatile("cp.async.cg.shared.global [%0], [%1], 16;\n" :: "r"(sa), "l"(gsrc));
}

__global__ void __launch_bounds__(NTHREADS, 1)
attn_pool_fused(const float* __restrict__ x, const float* __restrict__ seeds,
                float* __restrict__ out) {
    extern __shared__ float sm[];
    float* xs   = sm;                        // 2 * 32 * 512          = 32768 floats (swizzled)
    float* sd   = xs + 2 * TS * DD;          // 16 * 512              =  8192
    float* red  = sd + MM * DD;              // 8 * 32 * RSTRIDE      =  4352
    float* wd   = red + 8 * TS * RSTRIDE;    // 32 * 16               =   512
    float* lred = wd + TS * MM;              // 256
    float* linv = lred + NTHREADS;           // 16
    unsigned* flag = (unsigned*)(linv + MM); // 1

    const int t     = threadIdx.x;
    const int chunk = blockIdx.x;
    const int b     = blockIdx.y;
    const int w     = t >> 5;                // warp 0..7 (owns k-slice [64w,64w+64) in scores)
    const int l     = t & 31;                // lane = s-row owner in scores

    // seeds [16,512] -> smem, plain layout (score-phase reads are warp-uniform broadcasts)
    {
        const float4* s4 = (const float4*)seeds;
        float4* d4 = (float4*)sd;
#pragma unroll
        for (int i = 0; i < (MM * DD / 4) / NTHREADS; i++)   // 8
            d4[t + i * NTHREADS] = s4[t + i * NTHREADS];
    }

    const float4* xbase = (const float4*)(x + ((size_t)b * SS + (size_t)chunk * CSZ) * DD);

    // ---- async tile loader: XOR-swizzle float4 columns by (row & 7) ----
    auto issue_tile = [&](int tile, int buf) {
        const float4* src = xbase + (size_t)tile * TS * (DD / 4);
        float4* dst = (float4*)(xs + buf * TS * DD);
#pragma unroll
        for (int i = 0; i < (TS * DD / 4) / NTHREADS; i++) { // 16
            int idx = t + i * NTHREADS;
            int r = idx >> 7, c4 = idx & 127;
            cpasync16(&dst[r * 128 + (c4 ^ (r & 7))], &src[idx]);
        }
        asm volatile("cp.async.commit_group;\n" ::: "memory");
    };

    issue_tile(0, 0);

    unsigned long long accd0[8], accd1[8];   // (A[2j][d],A[2j+1][d]) for d=2t / 2t+1
#pragma unroll
    for (int j = 0; j < 8; j++) { accd0[j] = 0ull; accd1[j] = 0ull; }
    float lsum = 0.f;

    const int c4p = (t >> 1);                // accumulate-phase column (float4 units)
    const int halfoff = (t & 1) * 2;

    for (int tile = 0; tile < NT; ++tile) {
        const int cur = tile & 1;
        asm volatile("cp.async.wait_group 0;\n" ::: "memory");
        __syncthreads();   // buf[cur] visible; also: prev accumulate done -> safe to refill other buf
        if (tile + 1 < NT) issue_tile(tile + 1, (tile + 1) & 1);

        // ---- scores: lane owns s=l, warp owns k in [64w, 64w+64) ----
        {
            const float4* xb4 = (const float4*)(xs + cur * TS * DD) + l * 128;
            unsigned long long sacc[MM];
#pragma unroll
            for (int m = 0; m < MM; m++) sacc[m] = 0ull;
#pragma unroll 4
            for (int j = 0; j < 16; j++) {
                const int tk4 = (w << 4) + j;             // TRUE k-column (float4 units)
                const int c4 = tk4 ^ (l & 7);             // swizzled physical col for row l
                float4 xv = xb4[c4];                      // = x[s=l][4*tk4 .. 4*tk4+3]
                unsigned long long xp0 = packf2(xv.x, xv.y);
                unsigned long long xp1 = packf2(xv.z, xv.w);
                const float* sdk = sd + (tk4 << 2);       // seed indexed by TRUE k (warp-uniform)
#pragma unroll
                for (int m = 0; m < MM; m++) {
                    ulonglong2 sp = *(const ulonglong2*)(sdk + m * DD);
                    sacc[m] = ffma2(sp.x, xp0, sacc[m]);
                    sacc[m] = ffma2(sp.y, xp1, sacc[m]);
                }
            }
            float* rrow = red + (w * TS + l) * RSTRIDE;
#pragma unroll
            for (int m = 0; m < MM; m++)
                rrow[m] = lo2(sacc[m]) + hi2(sacc[m]);
        }
        __syncthreads();   // red complete

        // ---- reduce over 8 k-slices, exp, write weights (thread owns (s,m) pairs t, t+256) ----
        {
            const int s0 = t >> 4, m0 = t & 15;
            float a0 = 0.f, a1 = 0.f;
#pragma unroll
            for (int ww = 0; ww < 8; ww++) {
                a0 += red[(ww * TS + s0) * RSTRIDE + m0];
                a1 += red[(ww * TS + 16 + s0) * RSTRIDE + m0];
            }
            // scores bounded (|s| <= ~31): exp without max-subtraction is safe in fp32
            float e0 = __expf(a0), e1 = __expf(a1);
            wd[s0 * MM + m0] = e0;
            wd[(16 + s0) * MM + m0] = e1;
            lsum += e0 + e1;   // both pairs share m = t&15
        }
        __syncthreads();   // wd complete

        // ---- accumulate: acc[m][d] += w[s][m] * x[s][d], d = 2t,2t+1 ----
        {
            const float* xbf = xs + cur * TS * DD;
#pragma unroll 2
            for (int s = 0; s < TS; s++) {
                int cc = (c4p ^ (s & 7));
                float2 xv = *(const float2*)(xbf + s * DD + (cc << 2) + halfoff);
                unsigned long long xd0 = packf2(xv.x, xv.x);
                unsigned long long xd1 = packf2(xv.y, xv.y);
                const ulonglong2* wp = (const ulonglong2*)(wd + s * MM);
                ulonglong2 wa = wp[0], wb = wp[1], wc = wp[2], wdd = wp[3];
                accd0[0] = ffma2(wa.x, xd0, accd0[0]);  accd1[0] = ffma2(wa.x, xd1, accd1[0]);
                accd0[1] = ffma2(wa.y, xd0, accd0[1]);  accd1[1] = ffma2(wa.y, xd1, accd1[1]);
                accd0[2] = ffma2(wb.x, xd0, accd0[2]);  accd1[2] = ffma2(wb.x, xd1, accd1[2]);
                accd0[3] = ffma2(wb.y, xd0, accd0[3]);  accd1[3] = ffma2(wb.y, xd1, accd1[3]);
                accd0[4] = ffma2(wc.x, xd0, accd0[4]);  accd1[4] = ffma2(wc.x, xd1, accd1[4]);
                accd0[5] = ffma2(wc.y, xd0, accd0[5]);  accd1[5] = ffma2(wc.y, xd1, accd1[5]);
                accd0[6] = ffma2(wdd.x, xd0, accd0[6]); accd1[6] = ffma2(wdd.x, xd1, accd1[6]);
                accd0[7] = ffma2(wdd.y, xd0, accd0[7]); accd1[7] = ffma2(wdd.y, xd1, accd1[7]);
            }
        }
        // next-iter top sync separates this accumulate from wd/red rewrite + buffer refill
    }

    // ---- write per-chunk partials ----
    {
        size_t base = ((size_t)(b * CHUNKS + chunk) * MM) * DD;
#pragma unroll
        for (int j = 0; j < 8; j++) {
            *(float2*)&g_partA[base + (size_t)(2 * j) * DD + 2 * t] =
                make_float2(lo2(accd0[j]), lo2(accd1[j]));
            *(float2*)&g_partA[base + (size_t)(2 * j + 1) * DD + 2 * t] =
                make_float2(hi2(accd0[j]), hi2(accd1[j]));
        }
        lred[t] = lsum;
    }
    __syncthreads();
    if (t < MM) {
        float tot = 0.f;
#pragma unroll
        for (int i = 0; i < NTHREADS; i += MM) tot += lred[i + t];
        g_partL[(b * CHUNKS + chunk) * MM + t] = tot;
    }

    // ---- last-CTA-per-batch merge (single-kernel, deterministic) ----
    __threadfence();
    __syncthreads();
    if (t == 0) {
        unsigned old = atomicAdd(&g_cnt[b], 1u);
        flag[0] = ((old & (CHUNKS - 1)) == (CHUNKS - 1)) ? 1u : 0u;
    }
    __syncthreads();
    if (flag[0]) {
        __threadfence();
        if (t < MM) {
            float sl = 0.f;
#pragma unroll
            for (int c = 0; c < CHUNKS; c++)
                sl += g_partL[(b * CHUNKS + c) * MM + t];
            linv[t] = 1.f / sl;
        }
        __syncthreads();
        float4* ob = (float4*)(out + (size_t)b * MM * DD);
#pragma unroll
        for (int i = 0; i < 8; i++) {
            int o = t + i * NTHREADS;        // 0..2047 float4 over [MM][DD]
            int m = o >> 7, d4 = o & 127;
            float4 a = make_float4(0.f, 0.f, 0.f, 0.f);
#pragma unroll 8
            for (int c = 0; c < CHUNKS; c++) {
                const float4* pa =
                    (const float4*)&g_partA[(((size_t)(b * CHUNKS + c)) * MM + m) * DD];
                float4 v = pa[d4];
                a.x += v.x; a.y += v.y; a.z += v.z; a.w += v.w;
            }
            float inv = linv[m];
            ob[o] = make_float4(a.x * inv, a.y * inv, a.z * inv, a.w * inv);
        }
    }
}

extern "C" void kernel_launch(void* const* d_in, const int* in_sizes, int n_in,
                              void* d_out, int out_size) {
    const float* x     = (const float*)d_in[0];
    const float* seeds = (const float*)d_in[1];
    float* out = (float*)d_out;

    size_t smem = (size_t)(2 * TS * DD + MM * DD + 8 * TS * RSTRIDE + TS * MM
                           + NTHREADS + MM) * sizeof(float) + sizeof(unsigned);
    cudaFuncSetAttribute(attn_pool_fused,
                         cudaFuncAttributeMaxDynamicSharedMemorySize, (int)smem);

    dim3 grid(CHUNKS, BB);
    attn_pool_fused<<<grid, NTHREADS, smem>>>(x, seeds, out);
}

// round 6
// speedup vs baseline: 1.6369x; 1.0025x over previous
#include <cuda_runtime.h>

#define BB 32
#define SS 8192
#define DD 512
#define MM 16
#define CHUNKS 32
#define CSZ (SS/CHUNKS)      /* 256 */
#define TS 32
#define NT (CSZ/TS)          /* 8 tiles per chunk */
#define NTHREADS 256
#define RSTRIDE 17           /* red lane stride (floats): conflict-free STS.32 */

__device__ float g_partA[BB*CHUNKS*MM*DD];   // per-chunk weighted sums (33.5 MB)
__device__ float g_partL[BB*CHUNKS*MM];      // per-chunk sum of exp
__device__ unsigned g_cnt[BB];               // arrival counters (never reset; modulo trick)

__device__ __forceinline__ unsigned long long ffma2(unsigned long long a,
                                                    unsigned long long b,
                                                    unsigned long long c) {
    unsigned long long d;
    asm("fma.rn.f32x2 %0, %1, %2, %3;" : "=l"(d) : "l"(a), "l"(b), "l"(c));
    return d;
}
__device__ __forceinline__ float lo2(unsigned long long v) {
    return __uint_as_float((unsigned)(v & 0xffffffffull));
}
__device__ __forceinline__ float hi2(unsigned long long v) {
    return __uint_as_float((unsigned)(v >> 32));
}
__device__ __forceinline__ unsigned long long packf2(float lo, float hi) {
    return ((unsigned long long)__float_as_uint(hi) << 32) | __float_as_uint(lo);
}
__device__ __forceinline__ void cpasync16(void* sdst, const void* gsrc) {
    unsigned sa = (unsigned)__cvta_generic_to_shared(sdst);
    asm volatile("cp.async.cg.shared.global [%0], [%1], 16;\n" :: "r"(sa), "l"(gsrc));
}

__global__ void __launch_bounds__(NTHREADS, 1)
attn_pool_fused(const float* __restrict__ x, const float* __restrict__ seeds,
                float* __restrict__ out) {
    extern __shared__ float sm[];
    float* xs   = sm;                        // 2 * 32 * 512          = 32768 floats (swizzled)
    float* sd   = xs + 2 * TS * DD;          // 16 * 512              =  8192
    float* red  = sd + MM * DD;              // 8 * 32 * RSTRIDE      =  4352
    float* wd   = red + 8 * TS * RSTRIDE;    // 32 * 16               =   512
    float* lred = wd + TS * MM;              // 256
    float* linv = lred + NTHREADS;           // 16
    unsigned* flag = (unsigned*)(linv + MM); // 1

    const int t     = threadIdx.x;
    const int chunk = blockIdx.x;
    const int b     = blockIdx.y;
    const int w     = t >> 5;                // warp 0..7 (owns k-slice [64w,64w+64) in scores)
    const int l     = t & 31;                // lane = s-row owner in scores

    // seeds [16,512] -> smem, plain layout (score-phase reads are warp-uniform broadcasts)
    {
        const float4* s4 = (const float4*)seeds;
        float4* d4 = (float4*)sd;
#pragma unroll
        for (int i = 0; i < (MM * DD / 4) / NTHREADS; i++)   // 8
            d4[t + i * NTHREADS] = s4[t + i * NTHREADS];
    }

    const float4* xbase = (const float4*)(x + ((size_t)b * SS + (size_t)chunk * CSZ) * DD);

    // ---- async tile loader: XOR-swizzle float4 columns by (row & 7) ----
    auto issue_tile = [&](int tile, int buf) {
        const float4* src = xbase + (size_t)tile * TS * (DD / 4);
        float4* dst = (float4*)(xs + buf * TS * DD);
#pragma unroll
        for (int i = 0; i < (TS * DD / 4) / NTHREADS; i++) { // 16
            int idx = t + i * NTHREADS;
            int r = idx >> 7, c4 = idx & 127;
            cpasync16(&dst[r * 128 + (c4 ^ (r & 7))], &src[idx]);
        }
        asm volatile("cp.async.commit_group;\n" ::: "memory");
    };

    issue_tile(0, 0);

    unsigned long long accd0[8], accd1[8];   // (A[2j][d],A[2j+1][d]) for d=2t / 2t+1
#pragma unroll
    for (int j = 0; j < 8; j++) { accd0[j] = 0ull; accd1[j] = 0ull; }
    float lsum = 0.f;

    const int c4p = (t >> 1);                // accumulate-phase column (float4 units)
    const int halfoff = (t & 1) * 2;

    for (int tile = 0; tile < NT; ++tile) {
        const int cur = tile & 1;
        asm volatile("cp.async.wait_group 0;\n" ::: "memory");
        __syncthreads();   // buf[cur] visible; also: prev accumulate done -> safe to refill other buf
        if (tile + 1 < NT) issue_tile(tile + 1, (tile + 1) & 1);

        // ---- scores: lane owns s=l, warp owns k in [64w, 64w+64) ----
        {
            const float4* xb4 = (const float4*)(xs + cur * TS * DD) + l * 128;
            unsigned long long sacc[MM];
#pragma unroll
            for (int m = 0; m < MM; m++) sacc[m] = 0ull;
#pragma unroll 4
            for (int j = 0; j < 16; j++) {
                const int tk4 = (w << 4) + j;             // TRUE k-column (float4 units)
                const int c4 = tk4 ^ (l & 7);             // swizzled physical col for row l
                float4 xv = xb4[c4];                      // = x[s=l][4*tk4 .. 4*tk4+3]
                unsigned long long xp0 = packf2(xv.x, xv.y);
                unsigned long long xp1 = packf2(xv.z, xv.w);
                const float* sdk = sd + (tk4 << 2);       // seed indexed by TRUE k (warp-uniform)
#pragma unroll
                for (int m = 0; m < MM; m++) {
                    ulonglong2 sp = *(const ulonglong2*)(sdk + m * DD);
                    sacc[m] = ffma2(sp.x, xp0, sacc[m]);
                    sacc[m] = ffma2(sp.y, xp1, sacc[m]);
                }
            }
            float* rrow = red + (w * TS + l) * RSTRIDE;
#pragma unroll
            for (int m = 0; m < MM; m++)
                rrow[m] = lo2(sacc[m]) + hi2(sacc[m]);
        }
        __syncthreads();   // red complete

        // ---- reduce over 8 k-slices, exp, write weights (thread owns (s,m) pairs t, t+256) ----
        {
            const int s0 = t >> 4, m0 = t & 15;
            float a0 = 0.f, a1 = 0.f;
#pragma unroll
            for (int ww = 0; ww < 8; ww++) {
                a0 += red[(ww * TS + s0) * RSTRIDE + m0];
                a1 += red[(ww * TS + 16 + s0) * RSTRIDE + m0];
            }
            // scores bounded (|s| <= ~31): exp without max-subtraction is safe in fp32
            float e0 = __expf(a0), e1 = __expf(a1);
            wd[s0 * MM + m0] = e0;
            wd[(16 + s0) * MM + m0] = e1;
            lsum += e0 + e1;   // both pairs share m = t&15
        }
        __syncthreads();   // wd complete

        // ---- accumulate: acc[m][d] += w[s][m] * x[s][d], d = 2t,2t+1 ----
        {
            const float* xbf = xs + cur * TS * DD;
#pragma unroll 2
            for (int s = 0; s < TS; s++) {
                int cc = (c4p ^ (s & 7));
                float2 xv = *(const float2*)(xbf + s * DD + (cc << 2) + halfoff);
                unsigned long long xd0 = packf2(xv.x, xv.x);
                unsigned long long xd1 = packf2(xv.y, xv.y);
                const ulonglong2* wp = (const ulonglong2*)(wd + s * MM);
                ulonglong2 wa = wp[0], wb = wp[1], wc = wp[2], wdd = wp[3];
                accd0[0] = ffma2(wa.x, xd0, accd0[0]);  accd1[0] = ffma2(wa.x, xd1, accd1[0]);
                accd0[1] = ffma2(wa.y, xd0, accd0[1]);  accd1[1] = ffma2(wa.y, xd1, accd1[1]);
                accd0[2] = ffma2(wb.x, xd0, accd0[2]);  accd1[2] = ffma2(wb.x, xd1, accd1[2]);
                accd0[3] = ffma2(wb.y, xd0, accd0[3]);  accd1[3] = ffma2(wb.y, xd1, accd1[3]);
                accd0[4] = ffma2(wc.x, xd0, accd0[4]);  accd1[4] = ffma2(wc.x, xd1, accd1[4]);
                accd0[5] = ffma2(wc.y, xd0, accd0[5]);  accd1[5] = ffma2(wc.y, xd1, accd1[5]);
                accd0[6] = ffma2(wdd.x, xd0, accd0[6]); accd1[6] = ffma2(wdd.x, xd1, accd1[6]);
                accd0[7] = ffma2(wdd.y, xd0, accd0[7]); accd1[7] = ffma2(wdd.y, xd1, accd1[7]);
            }
        }
        // next-iter top sync separates this accumulate from wd/red rewrite + buffer refill
    }

    // ---- write per-chunk partials ----
    {
        size_t base = ((size_t)(b * CHUNKS + chunk) * MM) * DD;
#pragma unroll
        for (int j = 0; j < 8; j++) {
            *(float2*)&g_partA[base + (size_t)(2 * j) * DD + 2 * t] =
                make_float2(lo2(accd0[j]), lo2(accd1[j]));
            *(float2*)&g_partA[base + (size_t)(2 * j + 1) * DD + 2 * t] =
                make_float2(hi2(accd0[j]), hi2(accd1[j]));
        }
        lred[t] = lsum;
    }
    __syncthreads();
    if (t < MM) {
        float tot = 0.f;
#pragma unroll
        for (int i = 0; i < NTHREADS; i += MM) tot += lred[i + t];
        g_partL[(b * CHUNKS + chunk) * MM + t] = tot;
    }

    // ---- last-CTA-per-batch merge (single-kernel, deterministic) ----
    __threadfence();
    __syncthreads();
    if (t == 0) {
        unsigned old = atomicAdd(&g_cnt[b], 1u);
        flag[0] = ((old & (CHUNKS - 1)) == (CHUNKS - 1)) ? 1u : 0u;
    }
    __syncthreads();
    if (flag[0]) {
        __threadfence();
        if (t < MM) {
            float sl = 0.f;
#pragma unroll
            for (int c = 0; c < CHUNKS; c++)
                sl += g_partL[(b * CHUNKS + c) * MM + t];
            linv[t] = 1.f / sl;
        }
        __syncthreads();
        float4* ob = (float4*)(out + (size_t)b * MM * DD);
#pragma unroll
        for (int i = 0; i < 8; i++) {
            int o = t + i * NTHREADS;        // 0..2047 float4 over [MM][DD]
            int m = o >> 7, d4 = o & 127;
            float4 a = make_float4(0.f, 0.f, 0.f, 0.f);
#pragma unroll 8
            for (int c = 0; c < CHUNKS; c++) {
                const float4* pa =
                    (const float4*)&g_partA[(((size_t)(b * CHUNKS + c)) * MM + m) * DD];
                float4 v = pa[d4];
                a.x += v.x; a.y += v.y; a.z += v.z; a.w += v.w;
            }
            float inv = linv[m];
            ob[o] = make_float4(a.x * inv, a.y * inv, a.z * inv, a.w * inv);
        }
    }
}

extern "C" void kernel_launch(void* const* d_in, const int* in_sizes, int n_in,
                              void* d_out, int out_size) {
    const float* x     = (const float*)d_in[0];
    const float* seeds = (const float*)d_in[1];
    float* out = (float*)d_out;

    size_t smem = (size_t)(2 * TS * DD + MM * DD + 8 * TS * RSTRIDE + TS * MM
                           + NTHREADS + MM) * sizeof(float) + sizeof(unsigned);
    cudaFuncSetAttribute(attn_pool_fused,
                         cudaFuncAttributeMaxDynamicSharedMemorySize, (int)smem);

    dim3 grid(CHUNKS, BB);
    attn_pool_fused<<<grid, NTHREADS, smem>>>(x, seeds, out);
}

// round 7
// speedup vs baseline: 1.6381x; 1.0007x over previous
#include <cuda_runtime.h>

#define BB 32
#define SS 8192
#define DD 512
#define MM 16
#define CHUNKS 32
#define CSZ (SS/CHUNKS)      /* 256 */
#define TS 32
#define NT (CSZ/TS)          /* 8 tiles per chunk */
#define NTHREADS 256
#define RSTRIDE 17           /* red lane stride (floats): conflict-free STS.32 */

__device__ float g_partA[BB*CHUNKS*MM*DD];   // per-chunk weighted sums (33.5 MB)
__device__ float g_partL[BB*CHUNKS*MM];      // per-chunk sum of exp
__device__ unsigned g_cnt[BB];               // arrival counters (never reset; modulo trick)

__device__ __forceinline__ unsigned long long ffma2(unsigned long long a,
                                                    unsigned long long b,
                                                    unsigned long long c) {
    unsigned long long d;
    asm("fma.rn.f32x2 %0, %1, %2, %3;" : "=l"(d) : "l"(a), "l"(b), "l"(c));
    return d;
}
__device__ __forceinline__ float lo2(unsigned long long v) {
    return __uint_as_float((unsigned)(v & 0xffffffffull));
}
__device__ __forceinline__ float hi2(unsigned long long v) {
    return __uint_as_float((unsigned)(v >> 32));
}
__device__ __forceinline__ unsigned long long packf2(float lo, float hi) {
    return ((unsigned long long)__float_as_uint(hi) << 32) | __float_as_uint(lo);
}
__device__ __forceinline__ void cpasync16(void* sdst, const void* gsrc) {
    unsigned sa = (unsigned)__cvta_generic_to_shared(sdst);
    asm volatile("cp.async.cg.shared.global [%0], [%1], 16;\n" :: "r"(sa), "l"(gsrc));
}

__global__ void __launch_bounds__(NTHREADS, 1)
attn_pool_fused(const float* __restrict__ x, const float* __restrict__ seeds,
                float* __restrict__ out) {
    extern __shared__ float sm[];
    float* xs   = sm;                        // 2 * 32 * 512          = 32768 floats (swizzled)
    float* sd   = xs + 2 * TS * DD;          // 16 * 512              =  8192
    float* red  = sd + MM * DD;              // 8 * 32 * RSTRIDE      =  4352
    float* wd   = red + 8 * TS * RSTRIDE;    // 32 * 16               =   512
    float* lred = wd + TS * MM;              // 256
    float* linv = lred + NTHREADS;           // 16
    unsigned* flag = (unsigned*)(linv + MM); // 1

    const int t     = threadIdx.x;
    const int chunk = blockIdx.x;
    const int b     = blockIdx.y;
    const int w     = t >> 5;                // warp 0..7 (owns k-slice [64w,64w+64) in scores)
    const int l     = t & 31;                // lane = s-row owner in scores

    // seeds [16,512] -> smem, plain layout (score-phase reads are warp-uniform broadcasts)
    {
        const float4* s4 = (const float4*)seeds;
        float4* d4 = (float4*)sd;
#pragma unroll
        for (int i = 0; i < (MM * DD / 4) / NTHREADS; i++)   // 8
            d4[t + i * NTHREADS] = s4[t + i * NTHREADS];
    }

    const float4* xbase = (const float4*)(x + ((size_t)b * SS + (size_t)chunk * CSZ) * DD);

    // ---- async tile loader: XOR-swizzle float4 columns by (row & 7) ----
    auto issue_tile = [&](int tile, int buf) {
        const float4* src = xbase + (size_t)tile * TS * (DD / 4);
        float4* dst = (float4*)(xs + buf * TS * DD);
#pragma unroll
        for (int i = 0; i < (TS * DD / 4) / NTHREADS; i++) { // 16
            int idx = t + i * NTHREADS;
            int r = idx >> 7, c4 = idx & 127;
            cpasync16(&dst[r * 128 + (c4 ^ (r & 7))], &src[idx]);
        }
        asm volatile("cp.async.commit_group;\n" ::: "memory");
    };

    issue_tile(0, 0);

    unsigned long long accd0[8], accd1[8];   // (A[2j][d],A[2j+1][d]) for d=2t / 2t+1
#pragma unroll
    for (int j = 0; j < 8; j++) { accd0[j] = 0ull; accd1[j] = 0ull; }
    float lsum = 0.f;

    const int c4p = (t >> 1);                // accumulate-phase column (float4 units)
    const int halfoff = (t & 1) * 2;

    for (int tile = 0; tile < NT; ++tile) {
        const int cur = tile & 1;
        asm volatile("cp.async.wait_group 0;\n" ::: "memory");
        __syncthreads();   // buf[cur] visible; also: prev accumulate done -> safe to refill other buf
        if (tile + 1 < NT) issue_tile(tile + 1, (tile + 1) & 1);

        // ---- scores: lane owns s=l, warp owns k in [64w, 64w+64) ----
        {
            const float4* xb4 = (const float4*)(xs + cur * TS * DD) + l * 128;
            unsigned long long sacc[MM];
#pragma unroll
            for (int m = 0; m < MM; m++) sacc[m] = 0ull;
#pragma unroll 4
            for (int j = 0; j < 16; j++) {
                const int tk4 = (w << 4) + j;             // TRUE k-column (float4 units)
                const int c4 = tk4 ^ (l & 7);             // swizzled physical col for row l
                float4 xv = xb4[c4];                      // = x[s=l][4*tk4 .. 4*tk4+3]
                unsigned long long xp0 = packf2(xv.x, xv.y);
                unsigned long long xp1 = packf2(xv.z, xv.w);
                const float* sdk = sd + (tk4 << 2);       // seed indexed by TRUE k (warp-uniform)
#pragma unroll
                for (int m = 0; m < MM; m++) {
                    ulonglong2 sp = *(const ulonglong2*)(sdk + m * DD);
                    sacc[m] = ffma2(sp.x, xp0, sacc[m]);
                    sacc[m] = ffma2(sp.y, xp1, sacc[m]);
                }
            }
            float* rrow = red + (w * TS + l) * RSTRIDE;
#pragma unroll
            for (int m = 0; m < MM; m++)
                rrow[m] = lo2(sacc[m]) + hi2(sacc[m]);
        }
        __syncthreads();   // red complete

        // ---- reduce over 8 k-slices, exp, write weights (thread owns (s,m) pairs t, t+256) ----
        {
            const int s0 = t >> 4, m0 = t & 15;
            float a0 = 0.f, a1 = 0.f;
#pragma unroll
            for (int ww = 0; ww < 8; ww++) {
                a0 += red[(ww * TS + s0) * RSTRIDE + m0];
                a1 += red[(ww * TS + 16 + s0) * RSTRIDE + m0];
            }
            // scores bounded (|s| <= ~31): exp without max-subtraction is safe in fp32
            float e0 = __expf(a0), e1 = __expf(a1);
            wd[s0 * MM + m0] = e0;
            wd[(16 + s0) * MM + m0] = e1;
            lsum += e0 + e1;   // both pairs share m = t&15
        }
        __syncthreads();   // wd complete

        // ---- accumulate: acc[m][d] += w[s][m] * x[s][d], d = 2t,2t+1 ----
        {
            const float* xbf = xs + cur * TS * DD;
#pragma unroll 2
            for (int s = 0; s < TS; s++) {
                int cc = (c4p ^ (s & 7));
                float2 xv = *(const float2*)(xbf + s * DD + (cc << 2) + halfoff);
                unsigned long long xd0 = packf2(xv.x, xv.x);
                unsigned long long xd1 = packf2(xv.y, xv.y);
                const ulonglong2* wp = (const ulonglong2*)(wd + s * MM);
                ulonglong2 wa = wp[0], wb = wp[1], wc = wp[2], wdd = wp[3];
                accd0[0] = ffma2(wa.x, xd0, accd0[0]);  accd1[0] = ffma2(wa.x, xd1, accd1[0]);
                accd0[1] = ffma2(wa.y, xd0, accd0[1]);  accd1[1] = ffma2(wa.y, xd1, accd1[1]);
                accd0[2] = ffma2(wb.x, xd0, accd0[2]);  accd1[2] = ffma2(wb.x, xd1, accd1[2]);
                accd0[3] = ffma2(wb.y, xd0, accd0[3]);  accd1[3] = ffma2(wb.y, xd1, accd1[3]);
                accd0[4] = ffma2(wc.x, xd0, accd0[4]);  accd1[4] = ffma2(wc.x, xd1, accd1[4]);
                accd0[5] = ffma2(wc.y, xd0, accd0[5]);  accd1[5] = ffma2(wc.y, xd1, accd1[5]);
                accd0[6] = ffma2(wdd.x, xd0, accd0[6]); accd1[6] = ffma2(wdd.x, xd1, accd1[6]);
                accd0[7] = ffma2(wdd.y, xd0, accd0[7]); accd1[7] = ffma2(wdd.y, xd1, accd1[7]);
            }
        }
        // next-iter top sync separates this accumulate from wd/red rewrite + buffer refill
    }

    // ---- write per-chunk partials ----
    {
        size_t base = ((size_t)(b * CHUNKS + chunk) * MM) * DD;
#pragma unroll
        for (int j = 0; j < 8; j++) {
            *(float2*)&g_partA[base + (size_t)(2 * j) * DD + 2 * t] =
                make_float2(lo2(accd0[j]), lo2(accd1[j]));
            *(float2*)&g_partA[base + (size_t)(2 * j + 1) * DD + 2 * t] =
                make_float2(hi2(accd0[j]), hi2(accd1[j]));
        }
        lred[t] = lsum;
    }
    __syncthreads();
    if (t < MM) {
        float tot = 0.f;
#pragma unroll
        for (int i = 0; i < NTHREADS; i += MM) tot += lred[i + t];
        g_partL[(b * CHUNKS + chunk) * MM + t] = tot;
    }

    // ---- last-CTA-per-batch merge (single-kernel, deterministic) ----
    __threadfence();
    __syncthreads();
    if (t == 0) {
        unsigned old = atomicAdd(&g_cnt[b], 1u);
        flag[0] = ((old & (CHUNKS - 1)) == (CHUNKS - 1)) ? 1u : 0u;
    }
    __syncthreads();
    if (flag[0]) {
        __threadfence();
        if (t < MM) {
            float sl = 0.f;
#pragma unroll
            for (int c = 0; c < CHUNKS; c++)
                sl += g_partL[(b * CHUNKS + c) * MM + t];
            linv[t] = 1.f / sl;
        }
        __syncthreads();
        float4* ob = (float4*)(out + (size_t)b * MM * DD);
#pragma unroll
        for (int i = 0; i < 8; i++) {
            int o = t + i * NTHREADS;        // 0..2047 float4 over [MM][DD]
            int m = o >> 7, d4 = o & 127;
            float4 a = make_float4(0.f, 0.f, 0.f, 0.f);
#pragma unroll 8
            for (int c = 0; c < CHUNKS; c++) {
                const float4* pa =
                    (const float4*)&g_partA[(((size_t)(b * CHUNKS + c)) * MM + m) * DD];
                float4 v = pa[d4];
                a.x += v.x; a.y += v.y; a.z += v.z; a.w += v.w;
            }
            float inv = linv[m];
            ob[o] = make_float4(a.x * inv, a.y * inv, a.z * inv, a.w * inv);
        }
    }
}

extern "C" void kernel_launch(void* const* d_in, const int* in_sizes, int n_in,
                              void* d_out, int out_size) {
    const float* x     = (const float*)d_in[0];
    const float* seeds = (const float*)d_in[1];
    float* out = (float*)d_out;

    size_t smem = (size_t)(2 * TS * DD + MM * DD + 8 * TS * RSTRIDE + TS * MM
                           + NTHREADS + MM) * sizeof(float) + sizeof(unsigned);
    cudaFuncSetAttribute(attn_pool_fused,
                         cudaFuncAttributeMaxDynamicSharedMemorySize, (int)smem);

    dim3 grid(CHUNKS, BB);
    attn_pool_fused<<<grid, NTHREADS, smem>>>(x, seeds, out);
}

// round 8
// speedup vs baseline: 3.0914x; 1.8872x over previous
#include <cuda_runtime.h>
#include <cuda_bf16.h>
#include <stdint.h>

#define BB 32
#define SS 8192
#define DD 512
#define MM 16
#define CHUNKS 32
#define CSZ (SS/CHUNKS)      /* 256 */
#define TS 32
#define NT (CSZ/TS)          /* 8 */
#define NTHREADS 256

/* smem byte offsets */
#define OXH 0u               /* xh[2][32][512] bf16, swizzled, buf stride 32768 */
#define OXL 65536u           /* xl likewise */
#define OSH (OXH + 32768u)   /* seeds hi [16][520] bf16 (prologue only, in xh buf1) */
#define OSL (OXL + 32768u)   /* seeds lo (in xl buf1) */
#define ORED 131072u         /* fp32 [8][32][17] = 17408 B */
#define OPTH 148480u         /* P^T hi [16][40] bf16, row stride 80 B */
#define OPTL 149760u
#define OLRED 151040u        /* float[256] */
#define OLINV 152064u        /* float[16] */
#define OFLAG 152128u
#define SMEMSZ 152192u

__device__ float g_partA[BB*CHUNKS*MM*DD];
__device__ float g_partL[BB*CHUNKS*MM];
__device__ unsigned g_cnt[BB];

__device__ __forceinline__ unsigned sptr(const void* p) {
    return (unsigned)__cvta_generic_to_shared(p);
}
__device__ __forceinline__ void ldm_x4(unsigned* r, unsigned a) {
    asm volatile("ldmatrix.sync.aligned.m8n8.x4.shared.b16 {%0,%1,%2,%3}, [%4];"
                 : "=r"(r[0]), "=r"(r[1]), "=r"(r[2]), "=r"(r[3]) : "r"(a));
}
__device__ __forceinline__ void ldm_x2(unsigned* r, unsigned a) {
    asm volatile("ldmatrix.sync.aligned.m8n8.x2.shared.b16 {%0,%1}, [%2];"
                 : "=r"(r[0]), "=r"(r[1]) : "r"(a));
}
__device__ __forceinline__ void ldm_x2t(unsigned* r, unsigned a) {
    asm volatile("ldmatrix.sync.aligned.m8n8.x2.trans.shared.b16 {%0,%1}, [%2];"
                 : "=r"(r[0]), "=r"(r[1]) : "r"(a));
}
__device__ __forceinline__ void mma(float* c, const unsigned* a, const unsigned* b) {
    asm volatile("mma.sync.aligned.m16n8k16.row.col.f32.bf16.bf16.f32 "
                 "{%0,%1,%2,%3}, {%4,%5,%6,%7}, {%8,%9}, {%0,%1,%2,%3};"
                 : "+f"(c[0]), "+f"(c[1]), "+f"(c[2]), "+f"(c[3])
                 : "r"(a[0]), "r"(a[1]), "r"(a[2]), "r"(a[3]), "r"(b[0]), "r"(b[1]));
}
__device__ __forceinline__ void splitf4(float4 v, uint2& h, uint2& l) {
    __nv_bfloat162 h01 = __float22bfloat162_rn(make_float2(v.x, v.y));
    __nv_bfloat162 h23 = __float22bfloat162_rn(make_float2(v.z, v.w));
    float2 r01 = make_float2(v.x - __bfloat162float(h01.x), v.y - __bfloat162float(h01.y));
    float2 r23 = make_float2(v.z - __bfloat162float(h23.x), v.w - __bfloat162float(h23.y));
    __nv_bfloat162 l01 = __float22bfloat162_rn(r01);
    __nv_bfloat162 l23 = __float22bfloat162_rn(r23);
    h.x = *(unsigned*)&h01; h.y = *(unsigned*)&h23;
    l.x = *(unsigned*)&l01; l.y = *(unsigned*)&l23;
}

__global__ void __launch_bounds__(NTHREADS, 1)
attn_pool_mma(const float* __restrict__ x, const float* __restrict__ seeds,
              float* __restrict__ out) {
    extern __shared__ char smc[];
    const unsigned sb = sptr(smc);
    float* redp = (float*)(smc + ORED);
    float* lred = (float*)(smc + OLRED);
    float* linv = (float*)(smc + OLINV);
    unsigned* flag = (unsigned*)(smc + OFLAG);

    const int t = threadIdx.x, w = t >> 5, l = t & 31;
    const int chunk = blockIdx.x, b = blockIdx.y;
    const int lrow = (l & 7) + ((l >> 3) & 1) * 8;  /* x4 tile row */
    const int lsel = l >> 4;                        /* x4: k-granule select */
    const int qr = l >> 2, qc = (l & 3) * 2;        /* c-frag (row, col) base */

    const float4* xb4 = (const float4*)(x + ((size_t)b * SS + (size_t)chunk * CSZ) * DD);

    /* ---- prologue: stage seeds + tile0 via LDG ---- */
    float4 sg[8], g[16];
#pragma unroll
    for (int i = 0; i < 8; i++) sg[i] = ((const float4*)seeds)[t + i * 256];
#pragma unroll
    for (int i = 0; i < 16; i++) g[i] = xb4[t + i * 256];

    /* seeds -> bf16 hi/lo smem, padded rows (1040 B) */
#pragma unroll
    for (int i = 0; i < 8; i++) {
        int idx = t + i * 256, r = idx >> 7, c4 = idx & 127;
        uint2 h, lo;
        splitf4(sg[i], h, lo);
        *(uint2*)(smc + OSH + r * 1040 + c4 * 8) = h;
        *(uint2*)(smc + OSL + r * 1040 + c4 * 8) = lo;
    }
    __syncthreads();

    /* seed B-fragments (register-resident): [ks][nb]{2} */
    unsigned sbh[4][2][2], sbl[4][2][2];
#pragma unroll
    for (int ks = 0; ks < 4; ks++)
#pragma unroll
        for (int nb = 0; nb < 2; nb++) {
            int row = nb * 8 + (l & 7);
            int boff = (w * 64 + ks * 16) * 2 + ((l >> 3) & 1) * 16;
            ldm_x2(sbh[ks][nb], sb + OSH + row * 1040 + boff);
            ldm_x2(sbl[ks][nb], sb + OSL + row * 1040 + boff);
        }
    __syncthreads();   /* seed staging region free */

    /* tile0 -> bf16 smem buf0 (swizzled 16B granules) */
#pragma unroll
    for (int i = 0; i < 16; i++) {
        int idx = t + i * 256, r = idx >> 7, c4 = idx & 127;
        uint2 h, lo;
        splitf4(g[i], h, lo);
        unsigned off = r * 1024 + ((((unsigned)c4 >> 1) ^ (r & 7)) << 4) + (c4 & 1) * 8;
        *(uint2*)(smc + OXH + off) = h;
        *(uint2*)(smc + OXL + off) = lo;
    }
    __syncthreads();

    float acc[8][4];
#pragma unroll
    for (int i = 0; i < 8; i++)
#pragma unroll
        for (int j = 0; j < 4; j++) acc[i][j] = 0.f;
    float lsum = 0.f;

    for (int tile = 0; tile < NT; ++tile) {
        const unsigned cur = (tile & 1) * 32768u, nxt = ((tile + 1) & 1) * 32768u;
        if (tile + 1 < NT) {
#pragma unroll
            for (int i = 0; i < 16; i++)
                g[i] = xb4[(size_t)(tile + 1) * TS * 128 + t + i * 256];
        }

        /* ---- phase 1: scores partials, warp k-slice [64w,64w+64) ---- */
        float c[2][2][4];
#pragma unroll
        for (int mb = 0; mb < 2; mb++)
#pragma unroll
            for (int nb = 0; nb < 2; nb++)
#pragma unroll
                for (int j = 0; j < 4; j++) c[mb][nb][j] = 0.f;
#pragma unroll
        for (int ks = 0; ks < 4; ks++)
#pragma unroll
            for (int mb = 0; mb < 2; mb++) {
                int s = mb * 16 + lrow;
                unsigned gr = (unsigned)((8 * w + 2 * ks + lsel) ^ (s & 7));
                unsigned ah[4], al[4];
                ldm_x4(ah, sb + OXH + cur + s * 1024 + (gr << 4));
                ldm_x4(al, sb + OXL + cur + s * 1024 + (gr << 4));
                mma(c[mb][0], ah, sbh[ks][0]);
                mma(c[mb][0], ah, sbl[ks][0]);
                mma(c[mb][0], al, sbh[ks][0]);
                mma(c[mb][1], ah, sbh[ks][1]);
                mma(c[mb][1], ah, sbl[ks][1]);
                mma(c[mb][1], al, sbh[ks][1]);
            }
#pragma unroll
        for (int mb = 0; mb < 2; mb++)
#pragma unroll
            for (int nb = 0; nb < 2; nb++) {
                int i0 = w * 544 + (mb * 16 + qr) * 17 + nb * 8 + qc;
                redp[i0] = c[mb][nb][0];
                redp[i0 + 1] = c[mb][nb][1];
                redp[i0 + 8 * 17] = c[mb][nb][2];
                redp[i0 + 8 * 17 + 1] = c[mb][nb][3];
            }
        __syncthreads();

        /* ---- reduce over warps, exp, P^T hi/lo ---- */
        {
            int s0 = t >> 4, m0 = t & 15;
            float a0 = 0.f, a1 = 0.f;
#pragma unroll
            for (int ww = 0; ww < 8; ww++) {
                a0 += redp[ww * 544 + s0 * 17 + m0];
                a1 += redp[ww * 544 + (s0 + 16) * 17 + m0];
            }
            float e0 = __expf(a0), e1 = __expf(a1);
            lsum += e0 + e1;
            __nv_bfloat16 h0 = __float2bfloat16(e0), h1 = __float2bfloat16(e1);
            __nv_bfloat16 o0 = __float2bfloat16(e0 - __bfloat162float(h0));
            __nv_bfloat16 o1 = __float2bfloat16(e1 - __bfloat162float(h1));
            *(__nv_bfloat16*)(smc + OPTH + m0 * 80 + s0 * 2) = h0;
            *(__nv_bfloat16*)(smc + OPTH + m0 * 80 + (s0 + 16) * 2) = h1;
            *(__nv_bfloat16*)(smc + OPTL + m0 * 80 + s0 * 2) = o0;
            *(__nv_bfloat16*)(smc + OPTL + m0 * 80 + (s0 + 16) * 2) = o1;
        }
        __syncthreads();

        /* ---- phase 2: acc[16m, 64d slice] += P^T @ X ---- */
        unsigned pah[2][4], pal[2][4];
#pragma unroll
        for (int ks = 0; ks < 2; ks++) {
            unsigned ad = lrow * 80 + ks * 32 + lsel * 16;
            ldm_x4(pah[ks], sb + OPTH + ad);
            ldm_x4(pal[ks], sb + OPTL + ad);
        }
#pragma unroll
        for (int nt = 0; nt < 8; nt++) {
            int gn = 8 * w + nt;
#pragma unroll
            for (int ks = 0; ks < 2; ks++) {
                int sx = ks * 16 + (l & 15);
                unsigned ga = (unsigned)((gn ^ (sx & 7)) << 4);
                unsigned bh[2], bl[2];
                ldm_x2t(bh, sb + OXH + cur + sx * 1024 + ga);
                ldm_x2t(bl, sb + OXL + cur + sx * 1024 + ga);
                mma(acc[nt], pah[ks], bh);
                mma(acc[nt], pah[ks], bl);
                mma(acc[nt], pal[ks], bh);
            }
        }

        /* ---- convert + store next tile ---- */
        if (tile + 1 < NT) {
#pragma unroll
            for (int i = 0; i < 16; i++) {
                int idx = t + i * 256, r = idx >> 7, c4 = idx & 127;
                uint2 h, lo;
                splitf4(g[i], h, lo);
                unsigned off = nxt + r * 1024 +
                               ((((unsigned)c4 >> 1) ^ (r & 7)) << 4) + (c4 & 1) * 8;
                *(uint2*)(smc + OXH + off) = h;
                *(uint2*)(smc + OXL + off) = lo;
            }
        }
        __syncthreads();
    }

    /* ---- per-chunk partials ---- */
    {
        size_t base = ((size_t)(b * CHUNKS + chunk) * MM) * DD;
#pragma unroll
        for (int nt = 0; nt < 8; nt++) {
            int d0 = w * 64 + nt * 8 + qc;
            *(float2*)&g_partA[base + (size_t)qr * DD + d0] =
                make_float2(acc[nt][0], acc[nt][1]);
            *(float2*)&g_partA[base + (size_t)(qr + 8) * DD + d0] =
                make_float2(acc[nt][2], acc[nt][3]);
        }
        lred[t] = lsum;
    }
    __syncthreads();
    if (t < MM) {
        float tot = 0.f;
#pragma unroll
        for (int i = 0; i < NTHREADS; i += MM) tot += lred[i + t];
        g_partL[(b * CHUNKS + chunk) * MM + t] = tot;
    }

    /* ---- last-CTA-per-batch fused merge ---- */
    __threadfence();
    __syncthreads();
    if (t == 0) {
        unsigned old = atomicAdd(&g_cnt[b], 1u);
        flag[0] = ((old & (CHUNKS - 1)) == (CHUNKS - 1)) ? 1u : 0u;
    }
    __syncthreads();
    if (flag[0]) {
        __threadfence();
        if (t < MM) {
            float sl = 0.f;
#pragma unroll
            for (int c2 = 0; c2 < CHUNKS; c2++)
                sl += g_partL[(b * CHUNKS + c2) * MM + t];
            linv[t] = 1.f / sl;
        }
        __syncthreads();
        float4* ob = (float4*)(out + (size_t)b * MM * DD);
#pragma unroll
        for (int i = 0; i < 8; i++) {
            int o = t + i * NTHREADS;
            int m = o >> 7, d4 = o & 127;
            float4 a = make_float4(0.f, 0.f, 0.f, 0.f);
#pragma unroll 8
            for (int c2 = 0; c2 < CHUNKS; c2++) {
                const float4* pa =
                    (const float4*)&g_partA[(((size_t)(b * CHUNKS + c2)) * MM + m) * DD];
                float4 v = pa[d4];
                a.x += v.x; a.y += v.y; a.z += v.z; a.w += v.w;
            }
            float inv = linv[m];
            ob[o] = make_float4(a.x * inv, a.y * inv, a.z * inv, a.w * inv);
        }
    }
}

extern "C" void kernel_launch(void* const* d_in, const int* in_sizes, int n_in,
                              void* d_out, int out_size) {
    const float* x = (const float*)d_in[0];
    const float* seeds = (const float*)d_in[1];
    float* out = (float*)d_out;

    cudaFuncSetAttribute(attn_pool_mma,
                         cudaFuncAttributeMaxDynamicSharedMemorySize, (int)SMEMSZ);
    dim3 grid(CHUNKS, BB);
    attn_pool_mma<<<grid, NTHREADS, SMEMSZ>>>(x, seeds, out);
}